// round 1
// baseline (speedup 1.0000x reference)
#include <cuda_runtime.h>
#include <math.h>

#define TT   1024   // T
#define BB   32     // B
#define CC   1024   // feature dims (Q1=K1=V1=Q2=K2=V2)
#define KWW  3
#define NTC  16     // T-chunks for attend pass
#define TCH  64     // T per chunk (NTC*TCH = TT)

// ---------------- scratch (no allocations allowed) ----------------
__device__ __align__(16) float g_qT1[CC * BB];         // q1 transposed [k][b]
__device__ __align__(16) float g_qT2[CC * BB];         // q2 transposed [k][b]
__device__ __align__(16) float g_saq[BB * CC];         // sa(q1) [b][c]
__device__ __align__(16) float g_ker[BB * KWW * CC];   // conv kernels [b][w][c]
__device__ __align__(16) float g_a1r[TT * BB];         // raw additive logits
__device__ __align__(16) float g_s0[TT * BB];          // tap dot w=0
__device__ __align__(16) float g_s1[TT * BB];          // tap dot w=1
__device__ __align__(16) float g_s2[TT * BB];          // tap dot w=2
__device__ __align__(16) float g_e1[BB * TT];          // softmax weights path 1  [b][t]
__device__ __align__(16) float g_e2[BB * TT];          // softmax weights path 2  [b][t]
__device__ __align__(16) float g_part[NTC * BB * CC];  // attend partial sums

// ---------------- kernel 0: transpose q1,q2 to [k][b] ----------------
__global__ void k_transpose(const float* __restrict__ q1, const float* __restrict__ q2) {
    int idx = blockIdx.x * 256 + threadIdx.x;   // 0 .. 32767, layout [b][k]
    if (idx >= BB * CC) return;
    int b = idx >> 10;
    int k = idx & 1023;
    g_qT1[k * BB + b] = q1[idx];
    g_qT2[k * BB + b] = q2[idx];
}

// ---------------- kernel 1: row GEMMs (warp per weight row, lane = b) ----------------
// rows 0..1023   : saq[b][row]          = q1[b,:] . sa_w[row,:] + sa_b[row]
// rows 1024..4095: ker[b][w][c] (r=row-1024, c=r/3, w=r%3)
//                                        = q2[b,:] . qk_w[r,:]  + qk_b[r]
__global__ void __launch_bounds__(256) k_rowgemm(
    const float* __restrict__ sa_w, const float* __restrict__ sa_b,
    const float* __restrict__ qk_w, const float* __restrict__ qk_b) {
    int warp = (blockIdx.x * 256 + threadIdx.x) >> 5;
    int lane = threadIdx.x & 31;
    if (warp >= 4096) return;

    const float* wrow;
    const float* qT;
    float bias;
    if (warp < 1024) {
        wrow = sa_w + warp * CC;
        qT = g_qT1;
        bias = sa_b[warp];
    } else {
        int r = warp - 1024;
        wrow = qk_w + r * CC;
        qT = g_qT2;
        bias = qk_b[r];
    }

    float acc = 0.f;
#pragma unroll 4
    for (int k0 = 0; k0 < CC; k0 += 4) {
        float4 w4 = *(const float4*)(wrow + k0);   // uniform -> broadcast
        acc = fmaf(w4.x, qT[(k0 + 0) * BB + lane], acc);
        acc = fmaf(w4.y, qT[(k0 + 1) * BB + lane], acc);
        acc = fmaf(w4.z, qT[(k0 + 2) * BB + lane], acc);
        acc = fmaf(w4.w, qT[(k0 + 3) * BB + lane], acc);
    }
    acc += bias;

    if (warp < 1024) {
        g_saq[lane * CC + warp] = acc;
    } else {
        int r = warp - 1024;
        int c = r / KWW;
        int w = r % KWW;
        g_ker[(lane * KWW + w) * CC + c] = acc;
    }
}

// ---------------- kernel 2: big pass 1 — logits (streams k1 + k2) ----------------
// warp per (t,b):
//   a1r  = sum_c tanh(saq[b][c] + k1[t,b,c]) * a1_w[c]
//   s_w  = sum_c k2[t,b,c] * ker[b][w][c]    for w = 0,1,2
__global__ void __launch_bounds__(128) k_logits(
    const float* __restrict__ k1, const float* __restrict__ k2,
    const float* __restrict__ a1w) {
    int gw   = blockIdx.x * 4 + (threadIdx.x >> 5);
    int lane = threadIdx.x & 31;
    int t = gw >> 5;
    int b = gw & 31;

    const float4* k1p = (const float4*)(k1 + (size_t)(t * BB + b) * CC);
    const float4* k2p = (const float4*)(k2 + (size_t)(t * BB + b) * CC);
    const float4* sqp = (const float4*)(g_saq + b * CC);
    const float4* awp = (const float4*)a1w;
    const float4* kr0 = (const float4*)(g_ker + (b * KWW + 0) * CC);
    const float4* kr1 = (const float4*)(g_ker + (b * KWW + 1) * CC);
    const float4* kr2 = (const float4*)(g_ker + (b * KWW + 2) * CC);

    float a1 = 0.f, s0 = 0.f, s1 = 0.f, s2 = 0.f;
#pragma unroll
    for (int i = 0; i < 8; i++) {
        int c4 = i * 32 + lane;            // float4 index, coalesced per iteration
        float4 x1 = k1p[c4];
        float4 x2 = k2p[c4];
        float4 sv = sqp[c4];
        float4 av = awp[c4];
        float4 r0 = kr0[c4];
        float4 r1 = kr1[c4];
        float4 r2 = kr2[c4];

        a1 = fmaf(tanhf(sv.x + x1.x), av.x, a1);
        a1 = fmaf(tanhf(sv.y + x1.y), av.y, a1);
        a1 = fmaf(tanhf(sv.z + x1.z), av.z, a1);
        a1 = fmaf(tanhf(sv.w + x1.w), av.w, a1);

        s0 = fmaf(r0.x, x2.x, s0); s0 = fmaf(r0.y, x2.y, s0);
        s0 = fmaf(r0.z, x2.z, s0); s0 = fmaf(r0.w, x2.w, s0);
        s1 = fmaf(r1.x, x2.x, s1); s1 = fmaf(r1.y, x2.y, s1);
        s1 = fmaf(r1.z, x2.z, s1); s1 = fmaf(r1.w, x2.w, s1);
        s2 = fmaf(r2.x, x2.x, s2); s2 = fmaf(r2.y, x2.y, s2);
        s2 = fmaf(r2.z, x2.z, s2); s2 = fmaf(r2.w, x2.w, s2);
    }

#pragma unroll
    for (int o = 16; o > 0; o >>= 1) {
        a1 += __shfl_xor_sync(0xffffffffu, a1, o);
        s0 += __shfl_xor_sync(0xffffffffu, s0, o);
        s1 += __shfl_xor_sync(0xffffffffu, s1, o);
        s2 += __shfl_xor_sync(0xffffffffu, s2, o);
    }
    if (lane == 0) {
        int idx = t * BB + b;
        g_a1r[idx] = a1;
        g_s0[idx] = s0;
        g_s1[idx] = s1;
        g_s2[idx] = s2;
    }
}

// ---------------- kernel 3: masked softmax per b (block per b) ----------------
__device__ __forceinline__ float block_red(float v, float* red, int sum_mode) {
    int tid = threadIdx.x;
    red[tid] = v;
    __syncthreads();
#pragma unroll
    for (int s = 128; s > 0; s >>= 1) {
        if (tid < s)
            red[tid] = sum_mode ? (red[tid] + red[tid + s])
                                : fmaxf(red[tid], red[tid + s]);
        __syncthreads();
    }
    float r = red[0];
    __syncthreads();
    return r;
}

__global__ void __launch_bounds__(256) k_softmax(
    const float* __restrict__ k_mask, const float* __restrict__ a1_b) {
    __shared__ float red[256];
    int b = blockIdx.x;
    int tid = threadIdx.x;

    float va1[4], va2[4], mk[4];
    float m1 = -1e30f, m2 = -1e30f;
#pragma unroll
    for (int i = 0; i < 4; i++) {
        int t = i * 256 + tid;
        int idx = t * BB + b;
        va1[i] = g_a1r[idx] + a1_b[0];
        float a2 = g_s1[idx];
        if (t > 0)      a2 += g_s0[idx - BB];
        if (t < TT - 1) a2 += g_s2[idx + BB];
        va2[i] = a2;
        mk[i] = k_mask[idx];
        m1 = fmaxf(m1, va1[i]);
        m2 = fmaxf(m2, va2[i]);
    }
    m1 = block_red(m1, red, 0);
    m2 = block_red(m2, red, 0);

    float e1[4], e2[4];
    float sum1 = 0.f, sum2 = 0.f;
#pragma unroll
    for (int i = 0; i < 4; i++) {
        e1[i] = expf(va1[i] - m1) * mk[i];
        e2[i] = expf(va2[i] - m2) * mk[i];
        sum1 += e1[i];
        sum2 += e2[i];
    }
    sum1 = block_red(sum1, red, 1);
    sum2 = block_red(sum2, red, 1);
    float inv1 = 1.f / sum1;
    float inv2 = 1.f / sum2;

#pragma unroll
    for (int i = 0; i < 4; i++) {
        int t = i * 256 + tid;
        g_e1[b * TT + t] = e1[i] * inv1;
        g_e2[b * TT + t] = e2[i] * inv2;
    }
}

// ---------------- kernel 4: big pass 2 — attend (streams v1 + v2) ----------------
// block = (b, t-chunk); thread j owns float4 at d = 4j; partial sums to scratch.
__global__ void __launch_bounds__(256) k_attend(
    const float* __restrict__ v1, const float* __restrict__ v2) {
    int b  = blockIdx.x >> 4;
    int tc = blockIdx.x & (NTC - 1);
    int tid = threadIdx.x;

    __shared__ float se1[TCH], se2[TCH];
    if (tid < TCH)                    se1[tid] = g_e1[b * TT + tc * TCH + tid];
    else if (tid < 2 * TCH)           se2[tid - TCH] = g_e2[b * TT + tc * TCH + (tid - TCH)];
    __syncthreads();

    float4 acc = make_float4(0.f, 0.f, 0.f, 0.f);
#pragma unroll 4
    for (int tt = 0; tt < TCH; tt++) {
        int t = tc * TCH + tt;
        const float4* p1 = (const float4*)(v1 + ((size_t)(t * BB + b) << 10));
        const float4* p2 = (const float4*)(v2 + ((size_t)(t * BB + b) << 10));
        float4 a = p1[tid];
        float4 c = p2[tid];
        float w1 = se1[tt];
        float w2 = se2[tt];
        acc.x = fmaf(w1, a.x, fmaf(w2, c.x, acc.x));
        acc.y = fmaf(w1, a.y, fmaf(w2, c.y, acc.y));
        acc.z = fmaf(w1, a.z, fmaf(w2, c.z, acc.z));
        acc.w = fmaf(w1, a.w, fmaf(w2, c.w, acc.w));
    }
    ((float4*)g_part)[(tc * BB + b) * 256 + tid] = acc;
}

// ---------------- kernel 5: reduce partials + LayerNorm ----------------
__global__ void __launch_bounds__(256) k_final(
    const float* __restrict__ ln_g, const float* __restrict__ ln_b,
    float* __restrict__ out) {
    __shared__ float red[256];
    int b = blockIdx.x;
    int tid = threadIdx.x;

    float4 x = make_float4(0.f, 0.f, 0.f, 0.f);
#pragma unroll
    for (int tc = 0; tc < NTC; tc++) {
        float4 p = ((const float4*)g_part)[(tc * BB + b) * 256 + tid];
        x.x += p.x; x.y += p.y; x.z += p.z; x.w += p.w;
    }

    float s = x.x + x.y + x.z + x.w;
    float total = block_red(s, red, 1);
    float mu = total * (1.f / (float)CC);

    float dx0 = x.x - mu, dx1 = x.y - mu, dx2 = x.z - mu, dx3 = x.w - mu;
    float s2 = dx0 * dx0 + dx1 * dx1 + dx2 * dx2 + dx3 * dx3;
    float tot2 = block_red(s2, red, 1);
    float inv = rsqrtf(tot2 * (1.f / (float)CC) + 1e-6f);

    int d = tid * 4;
    float4 g = *(const float4*)(ln_g + d);
    float4 bb = *(const float4*)(ln_b + d);
    float4 o;
    o.x = dx0 * inv * g.x + bb.x;
    o.y = dx1 * inv * g.y + bb.y;
    o.z = dx2 * inv * g.z + bb.z;
    o.w = dx3 * inv * g.w + bb.w;
    *(float4*)(out + b * CC + d) = o;
}

// ---------------- launch ----------------
extern "C" void kernel_launch(void* const* d_in, const int* in_sizes, int n_in,
                              void* d_out, int out_size) {
    const float* q1     = (const float*)d_in[0];
    const float* k1     = (const float*)d_in[1];
    const float* v1     = (const float*)d_in[2];
    const float* q2     = (const float*)d_in[3];
    const float* k2     = (const float*)d_in[4];
    const float* v2     = (const float*)d_in[5];
    const float* k_mask = (const float*)d_in[6];
    const float* sa_w   = (const float*)d_in[7];
    const float* sa_b   = (const float*)d_in[8];
    const float* a1_w   = (const float*)d_in[9];
    const float* a1_b   = (const float*)d_in[10];
    const float* qk_w   = (const float*)d_in[11];
    const float* qk_b   = (const float*)d_in[12];
    const float* ln_g   = (const float*)d_in[13];
    const float* ln_b   = (const float*)d_in[14];
    float* out = (float*)d_out;

    k_transpose<<<(BB * CC + 255) / 256, 256>>>(q1, q2);
    k_rowgemm<<<512, 256>>>(sa_w, sa_b, qk_w, qk_b);
    k_logits<<<(TT * BB) / 4, 128>>>(k1, k2, a1_w);
    k_softmax<<<BB, 256>>>(k_mask, a1_b);
    k_attend<<<BB * NTC, 256>>>(v1, v2);
    k_final<<<BB, 256>>>(ln_g, ln_b, out);
}

// round 2
// speedup vs baseline: 1.0294x; 1.0294x over previous
#include <cuda_runtime.h>
#include <math.h>

#define TT   1024   // T
#define BB   32     // B
#define CC   1024   // feature dims (Q1=K1=V1=Q2=K2=V2)
#define KWW  3
#define NTC  16     // T-chunks for attend pass
#define TCH  64     // T per chunk (NTC*TCH = TT)
#define LTC  8      // logits t-chunks per b
#define LTCH 128    // t per logits block (LTC*LTCH = TT)

// ---------------- scratch (no allocations allowed) ----------------
__device__ __align__(16) float g_qT1[CC * BB];         // q1 transposed [k][b]
__device__ __align__(16) float g_qT2[CC * BB];         // q2 transposed [k][b]
__device__ __align__(16) float g_saq[BB * CC];         // sa(q1) [b][c]
__device__ __align__(16) float g_ker[BB * KWW * CC];   // conv kernels [b][w][c]
__device__ __align__(16) float g_a1r[BB * TT];         // raw additive logits [b][t]
__device__ __align__(16) float g_s0[BB * TT];          // tap dot w=0        [b][t]
__device__ __align__(16) float g_s1[BB * TT];          // tap dot w=1        [b][t]
__device__ __align__(16) float g_s2[BB * TT];          // tap dot w=2        [b][t]
__device__ __align__(16) float g_e1[BB * TT];          // softmax weights 1  [b][t]
__device__ __align__(16) float g_e2[BB * TT];          // softmax weights 2  [b][t]
__device__ __align__(16) float g_part[NTC * BB * CC];  // attend partial sums

__device__ __forceinline__ float tanh_approx(float x) {
    float y;
    asm("tanh.approx.f32 %0, %1;" : "=f"(y) : "f"(x));
    return y;
}

// ---------------- kernel 0: transpose q1,q2 to [k][b] ----------------
__global__ void k_transpose(const float* __restrict__ q1, const float* __restrict__ q2) {
    int idx = blockIdx.x * 256 + threadIdx.x;   // [b][k] layout in
    if (idx >= BB * CC) return;
    int b = idx >> 10;
    int k = idx & 1023;
    g_qT1[k * BB + b] = q1[idx];
    g_qT2[k * BB + b] = q2[idx];
}

// ---------------- kernel 1: row GEMMs (warp per weight row, lane = b) ----------------
__global__ void __launch_bounds__(256) k_rowgemm(
    const float* __restrict__ sa_w, const float* __restrict__ sa_b,
    const float* __restrict__ qk_w, const float* __restrict__ qk_b) {
    int warp = (blockIdx.x * 256 + threadIdx.x) >> 5;
    int lane = threadIdx.x & 31;
    if (warp >= 4096) return;

    const float* wrow;
    const float* qT;
    float bias;
    if (warp < 1024) {
        wrow = sa_w + warp * CC;
        qT = g_qT1;
        bias = sa_b[warp];
    } else {
        int r = warp - 1024;
        wrow = qk_w + r * CC;
        qT = g_qT2;
        bias = qk_b[r];
    }

    float acc = 0.f;
#pragma unroll 4
    for (int k0 = 0; k0 < CC; k0 += 4) {
        float4 w4 = *(const float4*)(wrow + k0);   // uniform -> broadcast
        acc = fmaf(w4.x, qT[(k0 + 0) * BB + lane], acc);
        acc = fmaf(w4.y, qT[(k0 + 1) * BB + lane], acc);
        acc = fmaf(w4.z, qT[(k0 + 2) * BB + lane], acc);
        acc = fmaf(w4.w, qT[(k0 + 3) * BB + lane], acc);
    }
    acc += bias;

    if (warp < 1024) {
        g_saq[lane * CC + warp] = acc;
    } else {
        int r = warp - 1024;
        int c = r / KWW;
        int w = r % KWW;
        g_ker[(lane * KWW + w) * CC + c] = acc;
    }
}

// ---------------- kernel 2: big pass 1 — logits (streams k1 + k2) ----------------
// block = (b, t-chunk of 128); side data (saq, a1w, ker taps) staged in smem ONCE.
// warp handles 16 t-rows; writes [b][t]-layout logits for coalesced softmax.
__global__ void __launch_bounds__(256) k_logits(
    const float* __restrict__ k1, const float* __restrict__ k2,
    const float* __restrict__ a1w) {
    __shared__ __align__(16) float s_sq[CC], s_aw[CC], s_r0[CC], s_r1[CC], s_r2[CC];

    int b  = blockIdx.x >> 3;
    int tc = blockIdx.x & (LTC - 1);
    int tid = threadIdx.x;

    {
        int i = tid;  // CC/4 == 256 == blockDim
        ((float4*)s_sq)[i] = ((const float4*)(g_saq + b * CC))[i];
        ((float4*)s_aw)[i] = ((const float4*)a1w)[i];
        ((float4*)s_r0)[i] = ((const float4*)(g_ker + (b * KWW + 0) * CC))[i];
        ((float4*)s_r1)[i] = ((const float4*)(g_ker + (b * KWW + 1) * CC))[i];
        ((float4*)s_r2)[i] = ((const float4*)(g_ker + (b * KWW + 2) * CC))[i];
    }
    __syncthreads();

    int warp = tid >> 5;
    int lane = tid & 31;

    for (int it = 0; it < LTCH / 8; ++it) {
        int t = tc * LTCH + it * 8 + warp;
        const float4* k1p = (const float4*)(k1 + (size_t)(t * BB + b) * CC);
        const float4* k2p = (const float4*)(k2 + (size_t)(t * BB + b) * CC);

        float a1 = 0.f, s0 = 0.f, s1 = 0.f, s2 = 0.f;
#pragma unroll
        for (int i = 0; i < 8; i++) {
            int c4 = i * 32 + lane;
            float4 x1 = k1p[c4];
            float4 x2 = k2p[c4];
            float4 sv = ((const float4*)s_sq)[c4];
            float4 av = ((const float4*)s_aw)[c4];
            float4 r0 = ((const float4*)s_r0)[c4];
            float4 r1 = ((const float4*)s_r1)[c4];
            float4 r2 = ((const float4*)s_r2)[c4];

            a1 = fmaf(tanh_approx(sv.x + x1.x), av.x, a1);
            a1 = fmaf(tanh_approx(sv.y + x1.y), av.y, a1);
            a1 = fmaf(tanh_approx(sv.z + x1.z), av.z, a1);
            a1 = fmaf(tanh_approx(sv.w + x1.w), av.w, a1);

            s0 = fmaf(r0.x, x2.x, s0); s0 = fmaf(r0.y, x2.y, s0);
            s0 = fmaf(r0.z, x2.z, s0); s0 = fmaf(r0.w, x2.w, s0);
            s1 = fmaf(r1.x, x2.x, s1); s1 = fmaf(r1.y, x2.y, s1);
            s1 = fmaf(r1.z, x2.z, s1); s1 = fmaf(r1.w, x2.w, s1);
            s2 = fmaf(r2.x, x2.x, s2); s2 = fmaf(r2.y, x2.y, s2);
            s2 = fmaf(r2.z, x2.z, s2); s2 = fmaf(r2.w, x2.w, s2);
        }

#pragma unroll
        for (int o = 16; o > 0; o >>= 1) {
            a1 += __shfl_xor_sync(0xffffffffu, a1, o);
            s0 += __shfl_xor_sync(0xffffffffu, s0, o);
            s1 += __shfl_xor_sync(0xffffffffu, s1, o);
            s2 += __shfl_xor_sync(0xffffffffu, s2, o);
        }
        if (lane == 0) {
            int idx = b * TT + t;   // [b][t] layout
            g_a1r[idx] = a1;
            g_s0[idx] = s0;
            g_s1[idx] = s1;
            g_s2[idx] = s2;
        }
    }
}

// ---------------- kernel 3: masked softmax per b (block per b) ----------------
__device__ __forceinline__ float block_red(float v, float* red, int sum_mode) {
    int tid = threadIdx.x;
    red[tid] = v;
    __syncthreads();
#pragma unroll
    for (int s = 128; s > 0; s >>= 1) {
        if (tid < s)
            red[tid] = sum_mode ? (red[tid] + red[tid + s])
                                : fmaxf(red[tid], red[tid + s]);
        __syncthreads();
    }
    float r = red[0];
    __syncthreads();
    return r;
}

__global__ void __launch_bounds__(256) k_softmax(
    const float* __restrict__ k_mask, const float* __restrict__ a1_b) {
    __shared__ float red[256];
    int b = blockIdx.x;
    int tid = threadIdx.x;

    float va1[4], va2[4], mk[4];
    float m1 = -1e30f, m2 = -1e30f;
#pragma unroll
    for (int i = 0; i < 4; i++) {
        int t = i * 256 + tid;
        int idx = b * TT + t;                       // coalesced
        va1[i] = g_a1r[idx] + a1_b[0];
        float a2 = g_s1[idx];
        if (t > 0)      a2 += g_s0[idx - 1];
        if (t < TT - 1) a2 += g_s2[idx + 1];
        va2[i] = a2;
        mk[i] = k_mask[t * BB + b];
        m1 = fmaxf(m1, va1[i]);
        m2 = fmaxf(m2, va2[i]);
    }
    m1 = block_red(m1, red, 0);
    m2 = block_red(m2, red, 0);

    float e1[4], e2[4];
    float sum1 = 0.f, sum2 = 0.f;
#pragma unroll
    for (int i = 0; i < 4; i++) {
        e1[i] = expf(va1[i] - m1) * mk[i];
        e2[i] = expf(va2[i] - m2) * mk[i];
        sum1 += e1[i];
        sum2 += e2[i];
    }
    sum1 = block_red(sum1, red, 1);
    sum2 = block_red(sum2, red, 1);
    float inv1 = 1.f / sum1;
    float inv2 = 1.f / sum2;

#pragma unroll
    for (int i = 0; i < 4; i++) {
        int t = i * 256 + tid;
        g_e1[b * TT + t] = e1[i] * inv1;
        g_e2[b * TT + t] = e2[i] * inv2;
    }
}

// ---------------- kernel 4: big pass 2 — attend (streams v1 + v2) ----------------
__global__ void __launch_bounds__(256) k_attend(
    const float* __restrict__ v1, const float* __restrict__ v2) {
    int b  = blockIdx.x >> 4;
    int tc = blockIdx.x & (NTC - 1);
    int tid = threadIdx.x;

    __shared__ float se1[TCH], se2[TCH];
    if (tid < TCH)           se1[tid] = g_e1[b * TT + tc * TCH + tid];
    else if (tid < 2 * TCH)  se2[tid - TCH] = g_e2[b * TT + tc * TCH + (tid - TCH)];
    __syncthreads();

    float4 acc = make_float4(0.f, 0.f, 0.f, 0.f);
#pragma unroll 4
    for (int tt = 0; tt < TCH; tt++) {
        int t = tc * TCH + tt;
        const float4* p1 = (const float4*)(v1 + ((size_t)(t * BB + b) << 10));
        const float4* p2 = (const float4*)(v2 + ((size_t)(t * BB + b) << 10));
        float4 a = p1[tid];
        float4 c = p2[tid];
        float w1 = se1[tt];
        float w2 = se2[tt];
        acc.x = fmaf(w1, a.x, fmaf(w2, c.x, acc.x));
        acc.y = fmaf(w1, a.y, fmaf(w2, c.y, acc.y));
        acc.z = fmaf(w1, a.z, fmaf(w2, c.z, acc.z));
        acc.w = fmaf(w1, a.w, fmaf(w2, c.w, acc.w));
    }
    ((float4*)g_part)[(tc * BB + b) * 256 + tid] = acc;
}

// ---------------- kernel 5: reduce partials + LayerNorm ----------------
__global__ void __launch_bounds__(256) k_final(
    const float* __restrict__ ln_g, const float* __restrict__ ln_b,
    float* __restrict__ out) {
    __shared__ float red[256];
    int b = blockIdx.x;
    int tid = threadIdx.x;

    float4 x = make_float4(0.f, 0.f, 0.f, 0.f);
#pragma unroll
    for (int tc = 0; tc < NTC; tc++) {
        float4 p = ((const float4*)g_part)[(tc * BB + b) * 256 + tid];
        x.x += p.x; x.y += p.y; x.z += p.z; x.w += p.w;
    }

    float s = x.x + x.y + x.z + x.w;
    float total = block_red(s, red, 1);
    float mu = total * (1.f / (float)CC);

    float dx0 = x.x - mu, dx1 = x.y - mu, dx2 = x.z - mu, dx3 = x.w - mu;
    float s2 = dx0 * dx0 + dx1 * dx1 + dx2 * dx2 + dx3 * dx3;
    float tot2 = block_red(s2, red, 1);
    float inv = rsqrtf(tot2 * (1.f / (float)CC) + 1e-6f);

    int d = tid * 4;
    float4 g = *(const float4*)(ln_g + d);
    float4 bb = *(const float4*)(ln_b + d);
    float4 o;
    o.x = dx0 * inv * g.x + bb.x;
    o.y = dx1 * inv * g.y + bb.y;
    o.z = dx2 * inv * g.z + bb.z;
    o.w = dx3 * inv * g.w + bb.w;
    *(float4*)(out + b * CC + d) = o;
}

// ---------------- launch ----------------
extern "C" void kernel_launch(void* const* d_in, const int* in_sizes, int n_in,
                              void* d_out, int out_size) {
    const float* q1     = (const float*)d_in[0];
    const float* k1     = (const float*)d_in[1];
    const float* v1     = (const float*)d_in[2];
    const float* q2     = (const float*)d_in[3];
    const float* k2     = (const float*)d_in[4];
    const float* v2     = (const float*)d_in[5];
    const float* k_mask = (const float*)d_in[6];
    const float* sa_w   = (const float*)d_in[7];
    const float* sa_b   = (const float*)d_in[8];
    const float* a1_w   = (const float*)d_in[9];
    const float* a1_b   = (const float*)d_in[10];
    const float* qk_w   = (const float*)d_in[11];
    const float* qk_b   = (const float*)d_in[12];
    const float* ln_g   = (const float*)d_in[13];
    const float* ln_b   = (const float*)d_in[14];
    float* out = (float*)d_out;

    k_transpose<<<(BB * CC + 255) / 256, 256>>>(q1, q2);
    k_rowgemm<<<512, 256>>>(sa_w, sa_b, qk_w, qk_b);
    k_logits<<<BB * LTC, 256>>>(k1, k2, a1_w);
    k_softmax<<<BB, 256>>>(k_mask, a1_b);
    k_attend<<<BB * NTC, 256>>>(v1, v2);
    k_final<<<BB, 256>>>(ln_g, ln_b, out);
}

// round 4
// speedup vs baseline: 1.0296x; 1.0002x over previous
#include <cuda_runtime.h>
#include <math.h>

#define TT   1024   // T
#define BB   32     // B
#define CC   1024   // feature dims
#define KWW  3
#define NTC  32     // T-chunks for attend pass
#define TCH  32     // T per attend chunk
#define LTC  32     // logits t-chunks per b
#define LTCH 32     // t per logits block

// ---------------- scratch (no allocations allowed) ----------------
__device__ __align__(16) float g_qT1[CC * BB];
__device__ __align__(16) float g_qT2[CC * BB];
__device__ __align__(16) float g_saq[BB * CC];         // sa(q1) [b][c]
__device__ __align__(16) float g_ker[BB * KWW * CC];   // conv kernels [b][w][c]
__device__ __align__(16) float g_a1r[BB * TT];         // [b][t]
__device__ __align__(16) float g_s0[BB * TT];
__device__ __align__(16) float g_s1[BB * TT];
__device__ __align__(16) float g_s2[BB * TT];
__device__ __align__(16) float g_e1[BB * TT];
__device__ __align__(16) float g_e2[BB * TT];
__device__ __align__(16) float g_part[NTC * BB * CC];  // attend partials

__device__ __forceinline__ float tanh_approx(float x) {
    float y;
    asm("tanh.approx.f32 %0, %1;" : "=f"(y) : "f"(x));
    return y;
}

// ---------------- kernel 0: transpose q1,q2 to [k][b] ----------------
__global__ void k_transpose(const float* __restrict__ q1, const float* __restrict__ q2) {
    int idx = blockIdx.x * 256 + threadIdx.x;
    if (idx >= BB * CC) return;
    int b = idx >> 10;
    int k = idx & 1023;
    g_qT1[k * BB + b] = q1[idx];
    g_qT2[k * BB + b] = q2[idx];
}

// ---------------- kernel 1: row GEMMs (warp per weight row, lane = b) ----------------
__global__ void __launch_bounds__(256) k_rowgemm(
    const float* __restrict__ sa_w, const float* __restrict__ sa_b,
    const float* __restrict__ qk_w, const float* __restrict__ qk_b) {
    int warp = (blockIdx.x * 256 + threadIdx.x) >> 5;
    int lane = threadIdx.x & 31;
    if (warp >= 4096) return;

    const float* wrow;
    const float* qT;
    float bias;
    if (warp < 1024) {
        wrow = sa_w + warp * CC;
        qT = g_qT1;
        bias = sa_b[warp];
    } else {
        int r = warp - 1024;
        wrow = qk_w + r * CC;
        qT = g_qT2;
        bias = qk_b[r];
    }

    float acc0 = 0.f, acc1 = 0.f;
#pragma unroll 4
    for (int k0 = 0; k0 < CC; k0 += 8) {
        float4 wa = *(const float4*)(wrow + k0);
        float4 wb = *(const float4*)(wrow + k0 + 4);
        acc0 = fmaf(wa.x, qT[(k0 + 0) * BB + lane], acc0);
        acc1 = fmaf(wa.y, qT[(k0 + 1) * BB + lane], acc1);
        acc0 = fmaf(wa.z, qT[(k0 + 2) * BB + lane], acc0);
        acc1 = fmaf(wa.w, qT[(k0 + 3) * BB + lane], acc1);
        acc0 = fmaf(wb.x, qT[(k0 + 4) * BB + lane], acc0);
        acc1 = fmaf(wb.y, qT[(k0 + 5) * BB + lane], acc1);
        acc0 = fmaf(wb.z, qT[(k0 + 6) * BB + lane], acc0);
        acc1 = fmaf(wb.w, qT[(k0 + 7) * BB + lane], acc1);
    }
    float acc = acc0 + acc1 + bias;

    if (warp < 1024) {
        g_saq[lane * CC + warp] = acc;
    } else {
        int r = warp - 1024;
        int c = r / KWW;
        int w = r % KWW;
        g_ker[(lane * KWW + w) * CC + c] = acc;
    }
}

// ---------------- kernel 2: logits (streams k1 + k2) ----------------
// block = (b, t-chunk of 32); side data staged in smem once per block.
__global__ void __launch_bounds__(256) k_logits(
    const float* __restrict__ k1, const float* __restrict__ k2,
    const float* __restrict__ a1w) {
    __shared__ __align__(16) float s_sq[CC], s_aw[CC], s_r0[CC], s_r1[CC], s_r2[CC];

    int b  = blockIdx.x >> 5;          // /LTC
    int tc = blockIdx.x & (LTC - 1);
    int tid = threadIdx.x;

    {
        int i = tid;  // CC/4 == 256 == blockDim
        ((float4*)s_sq)[i] = ((const float4*)(g_saq + b * CC))[i];
        ((float4*)s_aw)[i] = ((const float4*)a1w)[i];
        ((float4*)s_r0)[i] = ((const float4*)(g_ker + (b * KWW + 0) * CC))[i];
        ((float4*)s_r1)[i] = ((const float4*)(g_ker + (b * KWW + 1) * CC))[i];
        ((float4*)s_r2)[i] = ((const float4*)(g_ker + (b * KWW + 2) * CC))[i];
    }
    __syncthreads();

    int warp = tid >> 5;
    int lane = tid & 31;

#pragma unroll
    for (int it = 0; it < LTCH / 8; ++it) {
        int t = tc * LTCH + it * 8 + warp;
        const float4* k1p = (const float4*)(k1 + (size_t)(t * BB + b) * CC);
        const float4* k2p = (const float4*)(k2 + (size_t)(t * BB + b) * CC);

        float a1 = 0.f, s0 = 0.f, s1 = 0.f, s2 = 0.f;
#pragma unroll
        for (int i = 0; i < 8; i++) {
            int c4 = i * 32 + lane;
            float4 x1 = k1p[c4];
            float4 x2 = k2p[c4];
            float4 sv = ((const float4*)s_sq)[c4];
            float4 av = ((const float4*)s_aw)[c4];
            float4 r0 = ((const float4*)s_r0)[c4];
            float4 r1 = ((const float4*)s_r1)[c4];
            float4 r2 = ((const float4*)s_r2)[c4];

            a1 = fmaf(tanh_approx(sv.x + x1.x), av.x, a1);
            a1 = fmaf(tanh_approx(sv.y + x1.y), av.y, a1);
            a1 = fmaf(tanh_approx(sv.z + x1.z), av.z, a1);
            a1 = fmaf(tanh_approx(sv.w + x1.w), av.w, a1);

            s0 = fmaf(r0.x, x2.x, s0); s0 = fmaf(r0.y, x2.y, s0);
            s0 = fmaf(r0.z, x2.z, s0); s0 = fmaf(r0.w, x2.w, s0);
            s1 = fmaf(r1.x, x2.x, s1); s1 = fmaf(r1.y, x2.y, s1);
            s1 = fmaf(r1.z, x2.z, s1); s1 = fmaf(r1.w, x2.w, s1);
            s2 = fmaf(r2.x, x2.x, s2); s2 = fmaf(r2.y, x2.y, s2);
            s2 = fmaf(r2.z, x2.z, s2); s2 = fmaf(r2.w, x2.w, s2);
        }

#pragma unroll
        for (int o = 16; o > 0; o >>= 1) {
            a1 += __shfl_xor_sync(0xffffffffu, a1, o);
            s0 += __shfl_xor_sync(0xffffffffu, s0, o);
            s1 += __shfl_xor_sync(0xffffffffu, s1, o);
            s2 += __shfl_xor_sync(0xffffffffu, s2, o);
        }
        if (lane == 0) {
            int idx = b * TT + t;
            g_a1r[idx] = a1;
            g_s0[idx] = s0;
            g_s1[idx] = s1;
            g_s2[idx] = s2;
        }
    }
}

// ---------------- kernel 3: masked softmax (block per b) ----------------
// fast dual-value block reduction: warp shuffles + one smem stage
__device__ __forceinline__ void block_red2(float& v1, float& v2, float* sm, int sum_mode) {
    int lane = threadIdx.x & 31;
    int warp = threadIdx.x >> 5;
#pragma unroll
    for (int o = 16; o > 0; o >>= 1) {
        float o1 = __shfl_xor_sync(0xffffffffu, v1, o);
        float o2 = __shfl_xor_sync(0xffffffffu, v2, o);
        if (sum_mode) { v1 += o1; v2 += o2; }
        else          { v1 = fmaxf(v1, o1); v2 = fmaxf(v2, o2); }
    }
    if (lane == 0) { sm[warp] = v1; sm[8 + warp] = v2; }
    __syncthreads();
    float a = sm[lane & 7], bq = sm[8 + (lane & 7)];
#pragma unroll
    for (int o = 4; o > 0; o >>= 1) {
        float oa = __shfl_xor_sync(0xffffffffu, a, o);
        float ob = __shfl_xor_sync(0xffffffffu, bq, o);
        if (sum_mode) { a += oa; bq += ob; }
        else          { a = fmaxf(a, oa); bq = fmaxf(bq, ob); }
    }
    v1 = __shfl_sync(0xffffffffu, a, 0);
    v2 = __shfl_sync(0xffffffffu, bq, 0);
    __syncthreads();
}

__global__ void __launch_bounds__(256) k_softmax(
    const float* __restrict__ k_mask, const float* __restrict__ a1_b) {
    __shared__ float sm[16];
    int b = blockIdx.x;
    int tid = threadIdx.x;

    float va1[4], va2[4], mk[4];
    float m1 = -1e30f, m2 = -1e30f;
#pragma unroll
    for (int i = 0; i < 4; i++) {
        int t = i * 256 + tid;
        int idx = b * TT + t;
        va1[i] = g_a1r[idx] + a1_b[0];
        float a2 = g_s1[idx];
        if (t > 0)      a2 += g_s0[idx - 1];
        if (t < TT - 1) a2 += g_s2[idx + 1];
        va2[i] = a2;
        mk[i] = k_mask[t * BB + b];
        m1 = fmaxf(m1, va1[i]);
        m2 = fmaxf(m2, va2[i]);
    }
    block_red2(m1, m2, sm, 0);

    float e1[4], e2[4];
    float sum1 = 0.f, sum2 = 0.f;
#pragma unroll
    for (int i = 0; i < 4; i++) {
        e1[i] = expf(va1[i] - m1) * mk[i];
        e2[i] = expf(va2[i] - m2) * mk[i];
        sum1 += e1[i];
        sum2 += e2[i];
    }
    block_red2(sum1, sum2, sm, 1);
    float inv1 = 1.f / sum1;
    float inv2 = 1.f / sum2;

#pragma unroll
    for (int i = 0; i < 4; i++) {
        int t = i * 256 + tid;
        g_e1[b * TT + t] = e1[i] * inv1;
        g_e2[b * TT + t] = e2[i] * inv2;
    }
}

// ---------------- kernel 4: attend (streams v1 + v2) ----------------
__global__ void __launch_bounds__(256) k_attend(
    const float* __restrict__ v1, const float* __restrict__ v2) {
    int b  = blockIdx.x >> 5;          // /NTC
    int tc = blockIdx.x & (NTC - 1);
    int tid = threadIdx.x;

    __shared__ float se1[TCH], se2[TCH];
    if (tid < TCH)           se1[tid] = g_e1[b * TT + tc * TCH + tid];
    else if (tid < 2 * TCH)  se2[tid - TCH] = g_e2[b * TT + tc * TCH + (tid - TCH)];
    __syncthreads();

    float4 acc = make_float4(0.f, 0.f, 0.f, 0.f);
#pragma unroll 4
    for (int tt = 0; tt < TCH; tt++) {
        int t = tc * TCH + tt;
        const float4* p1 = (const float4*)(v1 + ((size_t)(t * BB + b) << 10));
        const float4* p2 = (const float4*)(v2 + ((size_t)(t * BB + b) << 10));
        float4 a = p1[tid];
        float4 c = p2[tid];
        float w1 = se1[tt];
        float w2 = se2[tt];
        acc.x = fmaf(w1, a.x, fmaf(w2, c.x, acc.x));
        acc.y = fmaf(w1, a.y, fmaf(w2, c.y, acc.y));
        acc.z = fmaf(w1, a.z, fmaf(w2, c.z, acc.z));
        acc.w = fmaf(w1, a.w, fmaf(w2, c.w, acc.w));
    }
    ((float4*)g_part)[(tc * BB + b) * 256 + tid] = acc;
}

// ---------------- kernel 5: reduce partials + LayerNorm ----------------
__device__ __forceinline__ float block_red1(float v, float* sm) {
    int lane = threadIdx.x & 31;
    int warp = threadIdx.x >> 5;
#pragma unroll
    for (int o = 16; o > 0; o >>= 1) v += __shfl_xor_sync(0xffffffffu, v, o);
    if (lane == 0) sm[warp] = v;
    __syncthreads();
    float a = sm[lane & 7];
#pragma unroll
    for (int o = 4; o > 0; o >>= 1) a += __shfl_xor_sync(0xffffffffu, a, o);
    a = __shfl_sync(0xffffffffu, a, 0);
    __syncthreads();
    return a;
}

__global__ void __launch_bounds__(256) k_final(
    const float* __restrict__ ln_g, const float* __restrict__ ln_b,
    float* __restrict__ out) {
    __shared__ float sm[8];
    int b = blockIdx.x;
    int tid = threadIdx.x;

    float4 x = make_float4(0.f, 0.f, 0.f, 0.f);
#pragma unroll
    for (int tc = 0; tc < NTC; tc++) {
        float4 p = ((const float4*)g_part)[(tc * BB + b) * 256 + tid];
        x.x += p.x; x.y += p.y; x.z += p.z; x.w += p.w;
    }

    float s = x.x + x.y + x.z + x.w;
    float total = block_red1(s, sm);
    float mu = total * (1.f / (float)CC);

    float dx0 = x.x - mu, dx1 = x.y - mu, dx2 = x.z - mu, dx3 = x.w - mu;
    float s2 = dx0 * dx0 + dx1 * dx1 + dx2 * dx2 + dx3 * dx3;
    float tot2 = block_red1(s2, sm);
    float inv = rsqrtf(tot2 * (1.f / (float)CC) + 1e-6f);

    int d = tid * 4;
    float4 g = *(const float4*)(ln_g + d);
    float4 bb = *(const float4*)(ln_b + d);
    float4 o;
    o.x = dx0 * inv * g.x + bb.x;
    o.y = dx1 * inv * g.y + bb.y;
    o.z = dx2 * inv * g.z + bb.z;
    o.w = dx3 * inv * g.w + bb.w;
    *(float4*)(out + b * CC + d) = o;
}

// ---------------- launch ----------------
extern "C" void kernel_launch(void* const* d_in, const int* in_sizes, int n_in,
                              void* d_out, int out_size) {
    const float* q1     = (const float*)d_in[0];
    const float* k1     = (const float*)d_in[1];
    const float* v1     = (const float*)d_in[2];
    const float* q2     = (const float*)d_in[3];
    const float* k2     = (const float*)d_in[4];
    const float* v2     = (const float*)d_in[5];
    const float* k_mask = (const float*)d_in[6];
    const float* sa_w   = (const float*)d_in[7];
    const float* sa_b   = (const float*)d_in[8];
    const float* a1_w   = (const float*)d_in[9];
    const float* a1_b   = (const float*)d_in[10];
    const float* qk_w   = (const float*)d_in[11];
    const float* qk_b   = (const float*)d_in[12];
    const float* ln_g   = (const float*)d_in[13];
    const float* ln_b   = (const float*)d_in[14];
    float* out = (float*)d_out;

    k_transpose<<<(BB * CC + 255) / 256, 256>>>(q1, q2);
    k_rowgemm<<<512, 256>>>(sa_w, sa_b, qk_w, qk_b);
    k_logits<<<BB * LTC, 256>>>(k1, k2, a1_w);
    k_softmax<<<BB, 256>>>(k_mask, a1_b);
    k_attend<<<BB * NTC, 256>>>(v1, v2);
    k_final<<<BB, 256>>>(ln_g, ln_b, out);
}